// round 4
// baseline (speedup 1.0000x reference)
#include <cuda_runtime.h>
#include <cuda_bf16.h>
#include <math.h>
#include <stdint.h>

// ---------------------------------------------------------------------------
// MyGAT: 3x GATConv (PyG, add_self_loops) + global mean pool + FC.
// N=50000, E=800000, F_in=128, L1: H=8,C=64 (concat), L2/L3: H=1,C=64,
// FC: 64->10, 64 graphs. Output [64,10] fp32.
// CSR-by-dst build + fused atomic-free softmax/aggregate per layer.
// This round: double-buffered 128-wide SGEMM + unrolled aggregation loops.
// ---------------------------------------------------------------------------

#define MAXN 50048
#define MAXE 800000
#define SCAN_B 512

__device__ float g_bufA[(size_t)MAXN * 512];
__device__ float g_bufB[(size_t)MAXN * 512];
__device__ float g_als[(size_t)MAXN * 8];
__device__ float g_ald[(size_t)MAXN * 8];
__device__ int   g_deg[MAXN];
__device__ int   g_incl[MAXN];
__device__ int   g_bsum[256];
__device__ int   g_bsumex[256];
__device__ int   g_rowptr[MAXN + 1];
__device__ int   g_cnt[MAXN];
__device__ int   g_srcs[MAXE];
__device__ float g_gsum[64 * 64];
__device__ float g_gcnt[64];

// ---------------------------------------------------------------------------
__global__ void fillf_k(float* p, long n, float v) {
    long i = (long)blockIdx.x * blockDim.x + threadIdx.x;
    if (i < n) p[i] = v;
}
__global__ void filli_k(int* p, int n, int v) {
    int i = blockIdx.x * blockDim.x + threadIdx.x;
    if (i < n) p[i] = v;
}

// ---------------------------------------------------------------------------
// CSR build
// ---------------------------------------------------------------------------
__global__ void hist_k(int E, const int* __restrict__ ei, int* deg) {
    int i = blockIdx.x * blockDim.x + threadIdx.x;
    if (i < E) atomicAdd(&deg[ei[E + i]], 1);
}

__global__ void scan1_k(const int* __restrict__ deg, int* incl, int* bsum, int n) {
    __shared__ int sh[SCAN_B];
    int t = threadIdx.x;
    int i = blockIdx.x * SCAN_B + t;
    sh[t] = (i < n) ? deg[i] : 0;
    __syncthreads();
#pragma unroll
    for (int off = 1; off < SCAN_B; off <<= 1) {
        int x = (t >= off) ? sh[t - off] : 0;
        __syncthreads();
        sh[t] += x;
        __syncthreads();
    }
    if (i < n) incl[i] = sh[t];
    if (t == SCAN_B - 1) bsum[blockIdx.x] = sh[t];
}

__global__ void scan2_k(const int* __restrict__ bsum, int* bsumex, int nb, int* rowptr) {
    if (threadIdx.x == 0 && blockIdx.x == 0) {
        int acc = 0;
        for (int b = 0; b < nb; b++) { bsumex[b] = acc; acc += bsum[b]; }
        rowptr[0] = 0;
    }
}

__global__ void scan3_k(const int* __restrict__ incl, const int* __restrict__ bsumex,
                        int* rowptr, int n) {
    int i = blockIdx.x * blockDim.x + threadIdx.x;
    if (i < n) rowptr[i + 1] = incl[i] + bsumex[i / SCAN_B];
}

__global__ void scatter_k(int E, const int* __restrict__ ei,
                          const int* __restrict__ rowptr, int* cnt, int* srcs) {
    int i = blockIdx.x * blockDim.x + threadIdx.x;
    if (i >= E) return;
    int d = ei[E + i];
    int pos = rowptr[d] + atomicAdd(&cnt[d], 1);
    srcs[pos] = ei[i];
}

// ---------------------------------------------------------------------------
// Double-buffered SGEMM: C[M,N] = A[M,K] @ B[K,N], row-major.
// BM x BN block tile, TM x TN micro-tile, BK=16. (BM/TM)*(BN/TN) threads.
// Requires N % BN == 0, K % BK == 0. M guarded.
// ---------------------------------------------------------------------------
template <int BM, int BN, int BK, int TM, int TN>
__global__ __launch_bounds__((BM / TM) * (BN / TN)) void sgemm2_k(
    int M, int N, int K,
    const float* __restrict__ A, const float* __restrict__ B,
    float* __restrict__ C) {
    constexpr int NT = (BM / TM) * (BN / TN);
    constexpr int LA = BM * BK / (4 * NT);   // float4 A loads per thread
    constexpr int LB = BK * BN / (4 * NT);   // float4 B loads per thread
    constexpr int KQ = BK / 4;               // float4 slots per A row

    __shared__ float As[2][BK][BM];
    __shared__ float Bs[2][BK][BN];

    const int tid = threadIdx.x;
    const int by = blockIdx.y * BM, bx = blockIdx.x * BN;
    const int tx = tid % (BN / TN), ty = tid / (BN / TN);

    // A-load coords (per slot): row = slot / KQ, kq = slot % KQ
    int a_row[LA], a_kq[LA];
#pragma unroll
    for (int i = 0; i < LA; i++) {
        int slot = tid + i * NT;
        a_row[i] = slot / KQ;
        a_kq[i] = slot % KQ;
    }
    // B-load coords: r = slot / (BN/4), cq = slot % (BN/4)
    int b_r[LB], b_cq[LB];
#pragma unroll
    for (int i = 0; i < LB; i++) {
        int slot = tid + i * NT;
        b_r[i] = slot / (BN / 4);
        b_cq[i] = slot % (BN / 4);
    }

    float4 a_stage[LA], b_stage[LB];

    auto load_regs = [&](int k0) {
#pragma unroll
        for (int i = 0; i < LA; i++) {
            int r = by + a_row[i];
            a_stage[i] = (r < M)
                ? *(const float4*)(A + (size_t)r * K + k0 + a_kq[i] * 4)
                : make_float4(0.f, 0.f, 0.f, 0.f);
        }
#pragma unroll
        for (int i = 0; i < LB; i++)
            b_stage[i] = *(const float4*)(B + (size_t)(k0 + b_r[i]) * N + bx + b_cq[i] * 4);
    };
    auto store_smem = [&](int buf) {
#pragma unroll
        for (int i = 0; i < LA; i++) {
            As[buf][a_kq[i] * 4 + 0][a_row[i]] = a_stage[i].x;
            As[buf][a_kq[i] * 4 + 1][a_row[i]] = a_stage[i].y;
            As[buf][a_kq[i] * 4 + 2][a_row[i]] = a_stage[i].z;
            As[buf][a_kq[i] * 4 + 3][a_row[i]] = a_stage[i].w;
        }
#pragma unroll
        for (int i = 0; i < LB; i++)
            *(float4*)&Bs[buf][b_r[i]][b_cq[i] * 4] = b_stage[i];
    };

    float acc[TM][TN] = {};
    load_regs(0);
    store_smem(0);
    __syncthreads();

    const int nk = K / BK;
    for (int t = 0; t < nk; t++) {
        int cur = t & 1;
        if (t + 1 < nk) load_regs((t + 1) * BK);
#pragma unroll
        for (int kk = 0; kk < BK; kk++) {
            float a[TM], b[TN];
#pragma unroll
            for (int i = 0; i < TM; i++) a[i] = As[cur][kk][ty * TM + i];
#pragma unroll
            for (int j = 0; j < TN; j++) b[j] = Bs[cur][kk][tx * TN + j];
#pragma unroll
            for (int i = 0; i < TM; i++)
#pragma unroll
                for (int j = 0; j < TN; j++) acc[i][j] += a[i] * b[j];
        }
        if (t + 1 < nk) store_smem(cur ^ 1);
        __syncthreads();
    }

#pragma unroll
    for (int i = 0; i < TM; i++) {
        int r = by + ty * TM + i;
        if (r >= M) continue;
#pragma unroll
        for (int j = 0; j < TN; j += 4) {
            float4 v = make_float4(acc[i][j], acc[i][j + 1], acc[i][j + 2], acc[i][j + 3]);
            *(float4*)(C + (size_t)r * N + bx + tx * TN + j) = v;
        }
    }
}

// ---------------------------------------------------------------------------
// Attention coefficients
// ---------------------------------------------------------------------------
template <int H, int C>
__global__ void compute_al_k(int N, const float* __restrict__ h,
                             const float* __restrict__ asrc,
                             const float* __restrict__ adst,
                             float* __restrict__ als, float* __restrict__ ald) {
    int w = (blockIdx.x * blockDim.x + threadIdx.x) >> 5;
    int lane = threadIdx.x & 31;
    if (w >= N * H) return;
    int hh = w % H;
    const float* hp = h + (size_t)w * C;
    float ss = 0.f, sd = 0.f;
#pragma unroll
    for (int c = lane; c < C; c += 32) {
        float v = hp[c];
        ss += v * asrc[hh * C + c];
        sd += v * adst[hh * C + c];
    }
#pragma unroll
    for (int o = 16; o > 0; o >>= 1) {
        ss += __shfl_down_sync(0xffffffffu, ss, o);
        sd += __shfl_down_sync(0xffffffffu, sd, o);
    }
    if (lane == 0) { als[w] = ss; ald[w] = sd; }
}

__device__ __forceinline__ float leaky(float e) { return (e > 0.f) ? e : 0.2f * e; }
__device__ __forceinline__ float elu(float v) { return (v > 0.f) ? v : expm1f(v); }

// ---------------------------------------------------------------------------
// Fused softmax+aggregate+bias+ELU, H=8,C=64. One 128-thread block per node.
// Unrolled x2 for MLP.
// ---------------------------------------------------------------------------
__global__ __launch_bounds__(128) void agg_h8_csr(
    int N, const int* __restrict__ rowptr, const int* __restrict__ srcs,
    const float* __restrict__ h, const float* __restrict__ als,
    const float* __restrict__ ald, const float* __restrict__ bias,
    float* __restrict__ out) {
    int d = blockIdx.x;
    int t = threadIdx.x;
    int hh = t >> 4;
    float aldv = __ldg(&ald[d * 8 + hh]);

    float ex = __expf(leaky(__ldg(&als[d * 8 + hh]) + aldv));
    float den = ex;
    float4 acc = ((const float4*)(h + (size_t)d * 512))[t];
    acc.x *= ex; acc.y *= ex; acc.z *= ex; acc.w *= ex;

    int beg = rowptr[d], end = rowptr[d + 1];
    int p = beg;
    for (; p + 2 <= end; p += 2) {
        int s0 = srcs[p], s1 = srcs[p + 1];
        float e0 = __expf(leaky(__ldg(&als[s0 * 8 + hh]) + aldv));
        float e1 = __expf(leaky(__ldg(&als[s1 * 8 + hh]) + aldv));
        float4 v0 = ((const float4*)(h + (size_t)s0 * 512))[t];
        float4 v1 = ((const float4*)(h + (size_t)s1 * 512))[t];
        den += e0 + e1;
        acc.x += e0 * v0.x + e1 * v1.x;
        acc.y += e0 * v0.y + e1 * v1.y;
        acc.z += e0 * v0.z + e1 * v1.z;
        acc.w += e0 * v0.w + e1 * v1.w;
    }
    if (p < end) {
        int s0 = srcs[p];
        float e0 = __expf(leaky(__ldg(&als[s0 * 8 + hh]) + aldv));
        float4 v0 = ((const float4*)(h + (size_t)s0 * 512))[t];
        den += e0;
        acc.x += e0 * v0.x; acc.y += e0 * v0.y;
        acc.z += e0 * v0.z; acc.w += e0 * v0.w;
    }
    float inv = 1.0f / den;
    float4 b = ((const float4*)bias)[t];
    float4 r;
    r.x = elu(acc.x * inv + b.x);
    r.y = elu(acc.y * inv + b.y);
    r.z = elu(acc.z * inv + b.z);
    r.w = elu(acc.w * inv + b.w);
    ((float4*)(out + (size_t)d * 512))[t] = r;
}

// Fused softmax+aggregate+bias+ELU, H=1,C=64. One warp per node. Unrolled x2.
__global__ __launch_bounds__(256) void agg_h1_csr(
    int N, const int* __restrict__ rowptr, const int* __restrict__ srcs,
    const float* __restrict__ h, const float* __restrict__ als,
    const float* __restrict__ ald, const float* __restrict__ bias,
    float* __restrict__ out) {
    int w = (blockIdx.x * blockDim.x + threadIdx.x) >> 5;
    int lane = threadIdx.x & 31;
    if (w >= N) return;
    int d = w;
    float aldv = __ldg(&ald[d]);

    float ex = __expf(leaky(__ldg(&als[d]) + aldv));
    float den = ex;
    float2 acc = ((const float2*)(h + (size_t)d * 64))[lane];
    acc.x *= ex; acc.y *= ex;

    int beg = rowptr[d], end = rowptr[d + 1];
    int p = beg;
    for (; p + 2 <= end; p += 2) {
        int s0 = srcs[p], s1 = srcs[p + 1];
        float e0 = __expf(leaky(__ldg(&als[s0]) + aldv));
        float e1 = __expf(leaky(__ldg(&als[s1]) + aldv));
        float2 v0 = ((const float2*)(h + (size_t)s0 * 64))[lane];
        float2 v1 = ((const float2*)(h + (size_t)s1 * 64))[lane];
        den += e0 + e1;
        acc.x += e0 * v0.x + e1 * v1.x;
        acc.y += e0 * v0.y + e1 * v1.y;
    }
    if (p < end) {
        int s0 = srcs[p];
        float e0 = __expf(leaky(__ldg(&als[s0]) + aldv));
        float2 v0 = ((const float2*)(h + (size_t)s0 * 64))[lane];
        den += e0;
        acc.x += e0 * v0.x; acc.y += e0 * v0.y;
    }
    float inv = 1.0f / den;
    float2 b = ((const float2*)bias)[lane];
    float2 r;
    r.x = elu(acc.x * inv + b.x);
    r.y = elu(acc.y * inv + b.y);
    ((float2*)(out + (size_t)d * 64))[lane] = r;
}

// ---------------------------------------------------------------------------
// Pool + FC
// ---------------------------------------------------------------------------
__global__ void pool_k(const float* __restrict__ h, const int* __restrict__ batch,
                       float* gsum, float* gcnt, int N) {
    int i = blockIdx.x * blockDim.x + threadIdx.x;
    if (i >= N * 64) return;
    int n = i >> 6, c = i & 63;
    int g = batch[n];
    atomicAdd(&gsum[g * 64 + c], h[i]);
    if (c == 0) atomicAdd(&gcnt[g], 1.0f);
}

__global__ void fc_k(const float* __restrict__ gsum, const float* __restrict__ gcnt,
                     const float* __restrict__ W, const float* __restrict__ b,
                     float* __restrict__ out) {
    int t = blockIdx.x * blockDim.x + threadIdx.x;
    if (t >= 640) return;
    int g = t / 10, o = t % 10;
    float inv = 1.0f / fmaxf(gcnt[g], 1.0f);
    float s = 0.f;
#pragma unroll
    for (int c = 0; c < 64; c++) s += (gsum[g * 64 + c] * inv) * W[c * 10 + o];
    out[t] = s + b[o];
}

// ---------------------------------------------------------------------------
// Host side
// ---------------------------------------------------------------------------
static inline void* symptr(const void* sym) {
    void* p = nullptr;
    cudaGetSymbolAddress(&p, sym);
    return p;
}
static inline int cdiv(long a, int b) { return (int)((a + b - 1) / b); }

extern "C" void kernel_launch(void* const* d_in, const int* in_sizes, int n_in,
                              void* d_out, int out_size) {
    const float* x   = (const float*)d_in[0];
    const int*   ei  = (const int*)d_in[1];
    const int*   bat = (const int*)d_in[2];
    const float* W1  = (const float*)d_in[3];
    const float* a1s = (const float*)d_in[4];
    const float* a1d = (const float*)d_in[5];
    const float* b1  = (const float*)d_in[6];
    const float* W2  = (const float*)d_in[7];
    const float* a2s = (const float*)d_in[8];
    const float* a2d = (const float*)d_in[9];
    const float* b2  = (const float*)d_in[10];
    const float* W3  = (const float*)d_in[11];
    const float* a3s = (const float*)d_in[12];
    const float* a3d = (const float*)d_in[13];
    const float* b3  = (const float*)d_in[14];
    const float* fcW = (const float*)d_in[15];
    const float* fcb = (const float*)d_in[16];

    const int N = in_sizes[0] / 128;
    const int E = in_sizes[1] / 2;

    float* bufA   = (float*)symptr(g_bufA);
    float* bufB   = (float*)symptr(g_bufB);
    float* als    = (float*)symptr(g_als);
    float* ald    = (float*)symptr(g_ald);
    int*   deg    = (int*)symptr(g_deg);
    int*   incl   = (int*)symptr(g_incl);
    int*   bsum   = (int*)symptr(g_bsum);
    int*   bsumex = (int*)symptr(g_bsumex);
    int*   rowptr = (int*)symptr(g_rowptr);
    int*   cnt    = (int*)symptr(g_cnt);
    int*   srcs   = (int*)symptr(g_srcs);
    float* gsum   = (float*)symptr(g_gsum);
    float* gcnt   = (float*)symptr(g_gcnt);

    const int TB = 256;
    const int nScanB = cdiv(N, SCAN_B);

    // ---------------- CSR build ----------------
    filli_k<<<cdiv(N, TB), TB>>>(deg, N, 0);
    filli_k<<<cdiv(N, TB), TB>>>(cnt, N, 0);
    hist_k<<<cdiv(E, TB), TB>>>(E, ei, deg);
    scan1_k<<<nScanB, SCAN_B>>>(deg, incl, bsum, N);
    scan2_k<<<1, 32>>>(bsum, bsumex, nScanB, rowptr);
    scan3_k<<<cdiv(N, TB), TB>>>(incl, bsumex, rowptr, N);
    scatter_k<<<cdiv(E, TB), TB>>>(E, ei, rowptr, cnt, srcs);

    // ---------------- Layer 1 (H=8, C=64, in=128) ----------------
    {
        dim3 grid(512 / 128, cdiv(N, 128));
        sgemm2_k<128, 128, 16, 8, 8><<<grid, 256>>>(N, 512, 128, x, W1, bufA);
    }
    compute_al_k<8, 64><<<cdiv((long)N * 8 * 32, TB), TB>>>(N, bufA, a1s, a1d, als, ald);
    agg_h8_csr<<<N, 128>>>(N, rowptr, srcs, bufA, als, ald, b1, bufB);

    // ---------------- Layer 2 (H=1, C=64, in=512) ----------------
    {
        dim3 grid(1, cdiv(N, 128));
        sgemm2_k<128, 64, 16, 8, 4><<<grid, 256>>>(N, 64, 512, bufB, W2, bufA);
    }
    compute_al_k<1, 64><<<cdiv((long)N * 32, TB), TB>>>(N, bufA, a2s, a2d, als, ald);
    agg_h1_csr<<<cdiv(N, 8), 256>>>(N, rowptr, srcs, bufA, als, ald, b2, bufB);

    // ---------------- Layer 3 (H=1, C=64, in=64) ----------------
    {
        dim3 grid(1, cdiv(N, 128));
        sgemm2_k<128, 64, 16, 8, 4><<<grid, 256>>>(N, 64, 64, bufB, W3, bufA);
    }
    compute_al_k<1, 64><<<cdiv((long)N * 32, TB), TB>>>(N, bufA, a3s, a3d, als, ald);
    agg_h1_csr<<<cdiv(N, 8), 256>>>(N, rowptr, srcs, bufA, als, ald, b3, bufB);

    // ---------------- Pool + FC ----------------
    fillf_k<<<16, 256>>>(gsum, 64 * 64, 0.f);
    fillf_k<<<1, 64>>>(gcnt, 64, 0.f);
    pool_k<<<cdiv((long)N * 64, TB), TB>>>(bufB, bat, gsum, gcnt, N);
    fc_k<<<3, 256>>>(gsum, gcnt, fcW, fcb, (float*)d_out);
}

// round 6
// speedup vs baseline: 1.1052x; 1.1052x over previous
#include <cuda_runtime.h>
#include <cuda_bf16.h>
#include <math.h>
#include <stdint.h>

// ---------------------------------------------------------------------------
// MyGAT: 3x GATConv (PyG, add_self_loops) + global mean pool + FC.
// N=50000, E=800000, F_in=128, L1: H=8,C=64 (concat), L2/L3: H=1,C=64,
// FC: 64->10, 64 graphs. Output [64,10] fp32.
// CSR-by-dst build + fused atomic-free softmax/aggregate per layer.
// R6 == R5 resubmission (infra failure): R3's proven 64x64 SGEMM +
// R4's unrolled aggregation (isolation round).
// ---------------------------------------------------------------------------

#define MAXN 50048
#define MAXE 800000
#define SCAN_B 512

__device__ float g_bufA[(size_t)MAXN * 512];
__device__ float g_bufB[(size_t)MAXN * 512];
__device__ float g_als[(size_t)MAXN * 8];
__device__ float g_ald[(size_t)MAXN * 8];
__device__ int   g_deg[MAXN];
__device__ int   g_incl[MAXN];
__device__ int   g_bsum[256];
__device__ int   g_bsumex[256];
__device__ int   g_rowptr[MAXN + 1];
__device__ int   g_cnt[MAXN];
__device__ int   g_srcs[MAXE];
__device__ float g_gsum[64 * 64];
__device__ float g_gcnt[64];

// ---------------------------------------------------------------------------
__global__ void fillf_k(float* p, long n, float v) {
    long i = (long)blockIdx.x * blockDim.x + threadIdx.x;
    if (i < n) p[i] = v;
}
__global__ void filli_k(int* p, int n, int v) {
    int i = blockIdx.x * blockDim.x + threadIdx.x;
    if (i < n) p[i] = v;
}

// ---------------------------------------------------------------------------
// CSR build
// ---------------------------------------------------------------------------
__global__ void hist_k(int E, const int* __restrict__ ei, int* deg) {
    int i = blockIdx.x * blockDim.x + threadIdx.x;
    if (i < E) atomicAdd(&deg[ei[E + i]], 1);
}

__global__ void scan1_k(const int* __restrict__ deg, int* incl, int* bsum, int n) {
    __shared__ int sh[SCAN_B];
    int t = threadIdx.x;
    int i = blockIdx.x * SCAN_B + t;
    sh[t] = (i < n) ? deg[i] : 0;
    __syncthreads();
#pragma unroll
    for (int off = 1; off < SCAN_B; off <<= 1) {
        int x = (t >= off) ? sh[t - off] : 0;
        __syncthreads();
        sh[t] += x;
        __syncthreads();
    }
    if (i < n) incl[i] = sh[t];
    if (t == SCAN_B - 1) bsum[blockIdx.x] = sh[t];
}

__global__ void scan2_k(const int* __restrict__ bsum, int* bsumex, int nb, int* rowptr) {
    if (threadIdx.x == 0 && blockIdx.x == 0) {
        int acc = 0;
        for (int b = 0; b < nb; b++) { bsumex[b] = acc; acc += bsum[b]; }
        rowptr[0] = 0;
    }
}

__global__ void scan3_k(const int* __restrict__ incl, const int* __restrict__ bsumex,
                        int* rowptr, int n) {
    int i = blockIdx.x * blockDim.x + threadIdx.x;
    if (i < n) rowptr[i + 1] = incl[i] + bsumex[i / SCAN_B];
}

__global__ void scatter_k(int E, const int* __restrict__ ei,
                          const int* __restrict__ rowptr, int* cnt, int* srcs) {
    int i = blockIdx.x * blockDim.x + threadIdx.x;
    if (i >= E) return;
    int d = ei[E + i];
    int pos = rowptr[d] + atomicAdd(&cnt[d], 1);
    srcs[pos] = ei[i];
}

// ---------------------------------------------------------------------------
// SGEMM (R3-proven): C[M,N] = A[M,K] @ B[K,N], row-major. K%16==0, N%64==0.
// ---------------------------------------------------------------------------
#define BM 64
#define BN 64
#define BK 16
__global__ __launch_bounds__(256) void sgemm_k(int M, int N, int K,
                                               const float* __restrict__ A,
                                               const float* __restrict__ B,
                                               float* __restrict__ C) {
    __shared__ float As[BK][BM + 4];
    __shared__ float Bs[BK][BN + 4];
    const int tid = threadIdx.x;
    const int brow = blockIdx.y * BM, bcol = blockIdx.x * BN;
    const int tx = tid & 15, ty = tid >> 4;
    const int arow = tid >> 2, acol = (tid & 3) << 2;
    const int brB = tid >> 4, bcB = (tid & 15) << 2;
    const int gArow = brow + arow;

    float acc[4][4] = {};
    for (int k0 = 0; k0 < K; k0 += BK) {
        float4 av = make_float4(0.f, 0.f, 0.f, 0.f);
        if (gArow < M) av = *(const float4*)(A + (size_t)gArow * K + k0 + acol);
        As[acol + 0][arow] = av.x; As[acol + 1][arow] = av.y;
        As[acol + 2][arow] = av.z; As[acol + 3][arow] = av.w;
        float4 bv = *(const float4*)(B + (size_t)(k0 + brB) * N + bcol + bcB);
        Bs[brB][bcB + 0] = bv.x; Bs[brB][bcB + 1] = bv.y;
        Bs[brB][bcB + 2] = bv.z; Bs[brB][bcB + 3] = bv.w;
        __syncthreads();
#pragma unroll
        for (int kk = 0; kk < BK; kk++) {
            float af[4], bf[4];
#pragma unroll
            for (int i = 0; i < 4; i++) af[i] = As[kk][ty * 4 + i];
#pragma unroll
            for (int j = 0; j < 4; j++) bf[j] = Bs[kk][tx * 4 + j];
#pragma unroll
            for (int i = 0; i < 4; i++)
#pragma unroll
                for (int j = 0; j < 4; j++) acc[i][j] += af[i] * bf[j];
        }
        __syncthreads();
    }
#pragma unroll
    for (int i = 0; i < 4; i++) {
        int r = brow + ty * 4 + i;
        if (r >= M) continue;
        float4 v = make_float4(acc[i][0], acc[i][1], acc[i][2], acc[i][3]);
        *(float4*)(C + (size_t)r * N + bcol + tx * 4) = v;
    }
}

// ---------------------------------------------------------------------------
// Attention coefficients
// ---------------------------------------------------------------------------
template <int H, int C>
__global__ void compute_al_k(int N, const float* __restrict__ h,
                             const float* __restrict__ asrc,
                             const float* __restrict__ adst,
                             float* __restrict__ als, float* __restrict__ ald) {
    int w = (blockIdx.x * blockDim.x + threadIdx.x) >> 5;
    int lane = threadIdx.x & 31;
    if (w >= N * H) return;
    int hh = w % H;
    const float* hp = h + (size_t)w * C;
    float ss = 0.f, sd = 0.f;
#pragma unroll
    for (int c = lane; c < C; c += 32) {
        float v = hp[c];
        ss += v * asrc[hh * C + c];
        sd += v * adst[hh * C + c];
    }
#pragma unroll
    for (int o = 16; o > 0; o >>= 1) {
        ss += __shfl_down_sync(0xffffffffu, ss, o);
        sd += __shfl_down_sync(0xffffffffu, sd, o);
    }
    if (lane == 0) { als[w] = ss; ald[w] = sd; }
}

__device__ __forceinline__ float leaky(float e) { return (e > 0.f) ? e : 0.2f * e; }
__device__ __forceinline__ float elu(float v) { return (v > 0.f) ? v : expm1f(v); }

// ---------------------------------------------------------------------------
// Fused softmax+aggregate+bias+ELU, H=8,C=64. One 128-thread block per node.
// Unrolled x2 for MLP.
// ---------------------------------------------------------------------------
__global__ __launch_bounds__(128) void agg_h8_csr(
    int N, const int* __restrict__ rowptr, const int* __restrict__ srcs,
    const float* __restrict__ h, const float* __restrict__ als,
    const float* __restrict__ ald, const float* __restrict__ bias,
    float* __restrict__ out) {
    int d = blockIdx.x;
    int t = threadIdx.x;
    int hh = t >> 4;
    float aldv = __ldg(&ald[d * 8 + hh]);

    float ex = __expf(leaky(__ldg(&als[d * 8 + hh]) + aldv));
    float den = ex;
    float4 acc = ((const float4*)(h + (size_t)d * 512))[t];
    acc.x *= ex; acc.y *= ex; acc.z *= ex; acc.w *= ex;

    int beg = rowptr[d], end = rowptr[d + 1];
    int p = beg;
    for (; p + 2 <= end; p += 2) {
        int s0 = srcs[p], s1 = srcs[p + 1];
        float e0 = __expf(leaky(__ldg(&als[s0 * 8 + hh]) + aldv));
        float e1 = __expf(leaky(__ldg(&als[s1 * 8 + hh]) + aldv));
        float4 v0 = ((const float4*)(h + (size_t)s0 * 512))[t];
        float4 v1 = ((const float4*)(h + (size_t)s1 * 512))[t];
        den += e0 + e1;
        acc.x += e0 * v0.x + e1 * v1.x;
        acc.y += e0 * v0.y + e1 * v1.y;
        acc.z += e0 * v0.z + e1 * v1.z;
        acc.w += e0 * v0.w + e1 * v1.w;
    }
    if (p < end) {
        int s0 = srcs[p];
        float e0 = __expf(leaky(__ldg(&als[s0 * 8 + hh]) + aldv));
        float4 v0 = ((const float4*)(h + (size_t)s0 * 512))[t];
        den += e0;
        acc.x += e0 * v0.x; acc.y += e0 * v0.y;
        acc.z += e0 * v0.z; acc.w += e0 * v0.w;
    }
    float inv = 1.0f / den;
    float4 b = ((const float4*)bias)[t];
    float4 r;
    r.x = elu(acc.x * inv + b.x);
    r.y = elu(acc.y * inv + b.y);
    r.z = elu(acc.z * inv + b.z);
    r.w = elu(acc.w * inv + b.w);
    ((float4*)(out + (size_t)d * 512))[t] = r;
}

// Fused softmax+aggregate+bias+ELU, H=1,C=64. One warp per node. Unrolled x2.
__global__ __launch_bounds__(256) void agg_h1_csr(
    int N, const int* __restrict__ rowptr, const int* __restrict__ srcs,
    const float* __restrict__ h, const float* __restrict__ als,
    const float* __restrict__ ald, const float* __restrict__ bias,
    float* __restrict__ out) {
    int w = (blockIdx.x * blockDim.x + threadIdx.x) >> 5;
    int lane = threadIdx.x & 31;
    if (w >= N) return;
    int d = w;
    float aldv = __ldg(&ald[d]);

    float ex = __expf(leaky(__ldg(&als[d]) + aldv));
    float den = ex;
    float2 acc = ((const float2*)(h + (size_t)d * 64))[lane];
    acc.x *= ex; acc.y *= ex;

    int beg = rowptr[d], end = rowptr[d + 1];
    int p = beg;
    for (; p + 2 <= end; p += 2) {
        int s0 = srcs[p], s1 = srcs[p + 1];
        float e0 = __expf(leaky(__ldg(&als[s0]) + aldv));
        float e1 = __expf(leaky(__ldg(&als[s1]) + aldv));
        float2 v0 = ((const float2*)(h + (size_t)s0 * 64))[lane];
        float2 v1 = ((const float2*)(h + (size_t)s1 * 64))[lane];
        den += e0 + e1;
        acc.x += e0 * v0.x + e1 * v1.x;
        acc.y += e0 * v0.y + e1 * v1.y;
    }
    if (p < end) {
        int s0 = srcs[p];
        float e0 = __expf(leaky(__ldg(&als[s0]) + aldv));
        float2 v0 = ((const float2*)(h + (size_t)s0 * 64))[lane];
        den += e0;
        acc.x += e0 * v0.x; acc.y += e0 * v0.y;
    }
    float inv = 1.0f / den;
    float2 b = ((const float2*)bias)[lane];
    float2 r;
    r.x = elu(acc.x * inv + b.x);
    r.y = elu(acc.y * inv + b.y);
    ((float2*)(out + (size_t)d * 64))[lane] = r;
}

// ---------------------------------------------------------------------------
// Pool + FC
// ---------------------------------------------------------------------------
__global__ void pool_k(const float* __restrict__ h, const int* __restrict__ batch,
                       float* gsum, float* gcnt, int N) {
    int i = blockIdx.x * blockDim.x + threadIdx.x;
    if (i >= N * 64) return;
    int n = i >> 6, c = i & 63;
    int g = batch[n];
    atomicAdd(&gsum[g * 64 + c], h[i]);
    if (c == 0) atomicAdd(&gcnt[g], 1.0f);
}

__global__ void fc_k(const float* __restrict__ gsum, const float* __restrict__ gcnt,
                     const float* __restrict__ W, const float* __restrict__ b,
                     float* __restrict__ out) {
    int t = blockIdx.x * blockDim.x + threadIdx.x;
    if (t >= 640) return;
    int g = t / 10, o = t % 10;
    float inv = 1.0f / fmaxf(gcnt[g], 1.0f);
    float s = 0.f;
#pragma unroll
    for (int c = 0; c < 64; c++) s += (gsum[g * 64 + c] * inv) * W[c * 10 + o];
    out[t] = s + b[o];
}

// ---------------------------------------------------------------------------
// Host side
// ---------------------------------------------------------------------------
static inline void* symptr(const void* sym) {
    void* p = nullptr;
    cudaGetSymbolAddress(&p, sym);
    return p;
}
static inline int cdiv(long a, int b) { return (int)((a + b - 1) / b); }

extern "C" void kernel_launch(void* const* d_in, const int* in_sizes, int n_in,
                              void* d_out, int out_size) {
    const float* x   = (const float*)d_in[0];
    const int*   ei  = (const int*)d_in[1];
    const int*   bat = (const int*)d_in[2];
    const float* W1  = (const float*)d_in[3];
    const float* a1s = (const float*)d_in[4];
    const float* a1d = (const float*)d_in[5];
    const float* b1  = (const float*)d_in[6];
    const float* W2  = (const float*)d_in[7];
    const float* a2s = (const float*)d_in[8];
    const float* a2d = (const float*)d_in[9];
    const float* b2  = (const float*)d_in[10];
    const float* W3  = (const float*)d_in[11];
    const float* a3s = (const float*)d_in[12];
    const float* a3d = (const float*)d_in[13];
    const float* b3  = (const float*)d_in[14];
    const float* fcW = (const float*)d_in[15];
    const float* fcb = (const float*)d_in[16];

    const int N = in_sizes[0] / 128;
    const int E = in_sizes[1] / 2;

    float* bufA   = (float*)symptr(g_bufA);
    float* bufB   = (float*)symptr(g_bufB);
    float* als    = (float*)symptr(g_als);
    float* ald    = (float*)symptr(g_ald);
    int*   deg    = (int*)symptr(g_deg);
    int*   incl   = (int*)symptr(g_incl);
    int*   bsum   = (int*)symptr(g_bsum);
    int*   bsumex = (int*)symptr(g_bsumex);
    int*   rowptr = (int*)symptr(g_rowptr);
    int*   cnt    = (int*)symptr(g_cnt);
    int*   srcs   = (int*)symptr(g_srcs);
    float* gsum   = (float*)symptr(g_gsum);
    float* gcnt   = (float*)symptr(g_gcnt);

    const int TB = 256;
    const int nScanB = cdiv(N, SCAN_B);

    // ---------------- CSR build ----------------
    filli_k<<<cdiv(N, TB), TB>>>(deg, N, 0);
    filli_k<<<cdiv(N, TB), TB>>>(cnt, N, 0);
    hist_k<<<cdiv(E, TB), TB>>>(E, ei, deg);
    scan1_k<<<nScanB, SCAN_B>>>(deg, incl, bsum, N);
    scan2_k<<<1, 32>>>(bsum, bsumex, nScanB, rowptr);
    scan3_k<<<cdiv(N, TB), TB>>>(incl, bsumex, rowptr, N);
    scatter_k<<<cdiv(E, TB), TB>>>(E, ei, rowptr, cnt, srcs);

    // ---------------- Layer 1 (H=8, C=64, in=128) ----------------
    {
        dim3 grid(512 / BN, cdiv(N, BM));
        sgemm_k<<<grid, 256>>>(N, 512, 128, x, W1, bufA);
    }
    compute_al_k<8, 64><<<cdiv((long)N * 8 * 32, TB), TB>>>(N, bufA, a1s, a1d, als, ald);
    agg_h8_csr<<<N, 128>>>(N, rowptr, srcs, bufA, als, ald, b1, bufB);

    // ---------------- Layer 2 (H=1, C=64, in=512) ----------------
    {
        dim3 grid(64 / BN, cdiv(N, BM));
        sgemm_k<<<grid, 256>>>(N, 64, 512, bufB, W2, bufA);
    }
    compute_al_k<1, 64><<<cdiv((long)N * 32, TB), TB>>>(N, bufA, a2s, a2d, als, ald);
    agg_h1_csr<<<cdiv(N, 8), 256>>>(N, rowptr, srcs, bufA, als, ald, b2, bufB);

    // ---------------- Layer 3 (H=1, C=64, in=64) ----------------
    {
        dim3 grid(64 / BN, cdiv(N, BM));
        sgemm_k<<<grid, 256>>>(N, 64, 64, bufB, W3, bufA);
    }
    compute_al_k<1, 64><<<cdiv((long)N * 32, TB), TB>>>(N, bufA, a3s, a3d, als, ald);
    agg_h1_csr<<<cdiv(N, 8), 256>>>(N, rowptr, srcs, bufA, als, ald, b3, bufB);

    // ---------------- Pool + FC ----------------
    fillf_k<<<16, 256>>>(gsum, 64 * 64, 0.f);
    fillf_k<<<1, 64>>>(gcnt, 64, 0.f);
    pool_k<<<cdiv((long)N * 64, TB), TB>>>(bufB, bat, gsum, gcnt, N);
    fc_k<<<3, 256>>>(gsum, gcnt, fcW, fcb, (float*)d_out);
}

// round 7
// speedup vs baseline: 1.5993x; 1.4471x over previous
#include <cuda_runtime.h>
#include <cuda_bf16.h>
#include <math.h>
#include <stdint.h>

// ---------------------------------------------------------------------------
// MyGAT: 3x GATConv (PyG, add_self_loops) + global mean pool + FC.
// N=50000, E=800000, F_in=128, L1: H=8,C=64 (concat), L2/L3: H=1,C=64,
// FC: 64->10, 64 graphs. Output [64,10] fp32.
// R7: tf32 tensor-core GEMM (mma.sync.m16n8k8) + run-length pool.
// Aggregation/CSR path identical to R6 (proven, 649 us).
// ---------------------------------------------------------------------------

#define MAXN 50048
#define MAXE 800000
#define SCAN_B 512

__device__ float g_bufA[(size_t)MAXN * 512];
__device__ float g_bufB[(size_t)MAXN * 512];
__device__ float g_als[(size_t)MAXN * 8];
__device__ float g_ald[(size_t)MAXN * 8];
__device__ int   g_deg[MAXN];
__device__ int   g_incl[MAXN];
__device__ int   g_bsum[256];
__device__ int   g_bsumex[256];
__device__ int   g_rowptr[MAXN + 1];
__device__ int   g_cnt[MAXN];
__device__ int   g_srcs[MAXE];
__device__ float g_gsum[64 * 64];
__device__ float g_gcnt[64];

// ---------------------------------------------------------------------------
__global__ void fillf_k(float* p, long n, float v) {
    long i = (long)blockIdx.x * blockDim.x + threadIdx.x;
    if (i < n) p[i] = v;
}
__global__ void filli_k(int* p, int n, int v) {
    int i = blockIdx.x * blockDim.x + threadIdx.x;
    if (i < n) p[i] = v;
}

// ---------------------------------------------------------------------------
// CSR build
// ---------------------------------------------------------------------------
__global__ void hist_k(int E, const int* __restrict__ ei, int* deg) {
    int i = blockIdx.x * blockDim.x + threadIdx.x;
    if (i < E) atomicAdd(&deg[ei[E + i]], 1);
}

__global__ void scan1_k(const int* __restrict__ deg, int* incl, int* bsum, int n) {
    __shared__ int sh[SCAN_B];
    int t = threadIdx.x;
    int i = blockIdx.x * SCAN_B + t;
    sh[t] = (i < n) ? deg[i] : 0;
    __syncthreads();
#pragma unroll
    for (int off = 1; off < SCAN_B; off <<= 1) {
        int x = (t >= off) ? sh[t - off] : 0;
        __syncthreads();
        sh[t] += x;
        __syncthreads();
    }
    if (i < n) incl[i] = sh[t];
    if (t == SCAN_B - 1) bsum[blockIdx.x] = sh[t];
}

__global__ void scan2_k(const int* __restrict__ bsum, int* bsumex, int nb, int* rowptr) {
    if (threadIdx.x == 0 && blockIdx.x == 0) {
        int acc = 0;
        for (int b = 0; b < nb; b++) { bsumex[b] = acc; acc += bsum[b]; }
        rowptr[0] = 0;
    }
}

__global__ void scan3_k(const int* __restrict__ incl, const int* __restrict__ bsumex,
                        int* rowptr, int n) {
    int i = blockIdx.x * blockDim.x + threadIdx.x;
    if (i < n) rowptr[i + 1] = incl[i] + bsumex[i / SCAN_B];
}

__global__ void scatter_k(int E, const int* __restrict__ ei,
                          const int* __restrict__ rowptr, int* cnt, int* srcs) {
    int i = blockIdx.x * blockDim.x + threadIdx.x;
    if (i >= E) return;
    int d = ei[E + i];
    int pos = rowptr[d] + atomicAdd(&cnt[d], 1);
    srcs[pos] = ei[i];
}

// ---------------------------------------------------------------------------
// tf32 tensor-core GEMM: C[M,N] = A[M,K] @ B[K,N], row-major fp32 in/out.
// Block tile 128x64, BK=32, 256 threads = 8 warps (4 along M, 2 along N).
// Warp tile 32x32 = 2(M) x 4(N) mma.m16n8k8 tiles.
// Requires K % 32 == 0, N % 64 == 0; M guarded.
// ---------------------------------------------------------------------------
__device__ __forceinline__ uint32_t f2tf32(float x) {
    uint32_t r;
    asm("cvt.rna.tf32.f32 %0, %1;" : "=r"(r) : "f"(x));
    return r;
}

#define AS_STRIDE 36
#define BS_STRIDE 68
__global__ __launch_bounds__(256, 2) void tf32gemm_k(
    int M, int N, int K,
    const float* __restrict__ A, const float* __restrict__ B,
    float* __restrict__ C) {
    __shared__ uint32_t As[128 * AS_STRIDE];   // [m][k], stride 36
    __shared__ uint32_t Bs[32 * BS_STRIDE];    // [k][n], stride 68

    const int tid = threadIdx.x;
    const int lane = tid & 31;
    const int warp = tid >> 5;
    const int wm = warp >> 1;       // 0..3
    const int wn = warp & 1;        // 0..1
    const int g = lane >> 2;        // 0..7
    const int t = lane & 3;         // 0..3
    const int by = blockIdx.y * 128, bx = blockIdx.x * 64;

    float acc[2][4][4];
#pragma unroll
    for (int mi = 0; mi < 2; mi++)
#pragma unroll
        for (int ni = 0; ni < 4; ni++)
#pragma unroll
            for (int j = 0; j < 4; j++) acc[mi][ni][j] = 0.f;

    // A-load mapping: 128 rows x 8 float4-cols; 256 threads -> 32 rows/iter
    const int ar = tid >> 3, ac4 = tid & 7;
    // B-load mapping: 32 rows x 16 float4-cols; 256 threads -> 16 rows/iter
    const int br = tid >> 4, bc4 = tid & 15;

    for (int k0 = 0; k0 < K; k0 += 32) {
#pragma unroll
        for (int it = 0; it < 4; it++) {
            int row = it * 32 + ar;
            int gr = by + row;
            float4 v = make_float4(0.f, 0.f, 0.f, 0.f);
            if (gr < M) v = *(const float4*)(A + (size_t)gr * K + k0 + ac4 * 4);
            uint32_t* p = &As[row * AS_STRIDE + ac4 * 4];
            p[0] = f2tf32(v.x); p[1] = f2tf32(v.y);
            p[2] = f2tf32(v.z); p[3] = f2tf32(v.w);
        }
#pragma unroll
        for (int it = 0; it < 2; it++) {
            int row = it * 16 + br;
            float4 v = *(const float4*)(B + (size_t)(k0 + row) * N + bx + bc4 * 4);
            uint32_t* p = &Bs[row * BS_STRIDE + bc4 * 4];
            p[0] = f2tf32(v.x); p[1] = f2tf32(v.y);
            p[2] = f2tf32(v.z); p[3] = f2tf32(v.w);
        }
        __syncthreads();

#pragma unroll
        for (int ks = 0; ks < 4; ks++) {
            uint32_t a[2][4];
#pragma unroll
            for (int mi = 0; mi < 2; mi++) {
                int r0 = wm * 32 + mi * 16 + g;
                int kk = ks * 8 + t;
                a[mi][0] = As[r0 * AS_STRIDE + kk];
                a[mi][1] = As[(r0 + 8) * AS_STRIDE + kk];
                a[mi][2] = As[r0 * AS_STRIDE + kk + 4];
                a[mi][3] = As[(r0 + 8) * AS_STRIDE + kk + 4];
            }
            uint32_t b[4][2];
#pragma unroll
            for (int ni = 0; ni < 4; ni++) {
                int c0 = wn * 32 + ni * 8 + g;
                int kk = ks * 8 + t;
                b[ni][0] = Bs[kk * BS_STRIDE + c0];
                b[ni][1] = Bs[(kk + 4) * BS_STRIDE + c0];
            }
#pragma unroll
            for (int mi = 0; mi < 2; mi++)
#pragma unroll
                for (int ni = 0; ni < 4; ni++) {
                    asm volatile(
                        "mma.sync.aligned.m16n8k8.row.col.f32.tf32.tf32.f32 "
                        "{%0,%1,%2,%3}, {%4,%5,%6,%7}, {%8,%9}, {%0,%1,%2,%3};"
                        : "+f"(acc[mi][ni][0]), "+f"(acc[mi][ni][1]),
                          "+f"(acc[mi][ni][2]), "+f"(acc[mi][ni][3])
                        : "r"(a[mi][0]), "r"(a[mi][1]), "r"(a[mi][2]), "r"(a[mi][3]),
                          "r"(b[ni][0]), "r"(b[ni][1]));
                }
        }
        __syncthreads();
    }

    // Epilogue: c0/c1 -> (row g, cols 2t,2t+1); c2/c3 -> (row g+8, same cols)
#pragma unroll
    for (int mi = 0; mi < 2; mi++) {
        int r0 = by + wm * 32 + mi * 16 + g;
        int r1 = r0 + 8;
#pragma unroll
        for (int ni = 0; ni < 4; ni++) {
            int col = bx + wn * 32 + ni * 8 + 2 * t;
            if (r0 < M)
                *(float2*)(C + (size_t)r0 * N + col) =
                    make_float2(acc[mi][ni][0], acc[mi][ni][1]);
            if (r1 < M)
                *(float2*)(C + (size_t)r1 * N + col) =
                    make_float2(acc[mi][ni][2], acc[mi][ni][3]);
        }
    }
}

// ---------------------------------------------------------------------------
// Attention coefficients
// ---------------------------------------------------------------------------
template <int H, int C>
__global__ void compute_al_k(int N, const float* __restrict__ h,
                             const float* __restrict__ asrc,
                             const float* __restrict__ adst,
                             float* __restrict__ als, float* __restrict__ ald) {
    int w = (blockIdx.x * blockDim.x + threadIdx.x) >> 5;
    int lane = threadIdx.x & 31;
    if (w >= N * H) return;
    int hh = w % H;
    const float* hp = h + (size_t)w * C;
    float ss = 0.f, sd = 0.f;
#pragma unroll
    for (int c = lane; c < C; c += 32) {
        float v = hp[c];
        ss += v * asrc[hh * C + c];
        sd += v * adst[hh * C + c];
    }
#pragma unroll
    for (int o = 16; o > 0; o >>= 1) {
        ss += __shfl_down_sync(0xffffffffu, ss, o);
        sd += __shfl_down_sync(0xffffffffu, sd, o);
    }
    if (lane == 0) { als[w] = ss; ald[w] = sd; }
}

__device__ __forceinline__ float leaky(float e) { return (e > 0.f) ? e : 0.2f * e; }
__device__ __forceinline__ float elu(float v) { return (v > 0.f) ? v : expm1f(v); }

// ---------------------------------------------------------------------------
// Fused softmax+aggregate+bias+ELU, H=8,C=64. One 128-thread block per node.
// ---------------------------------------------------------------------------
__global__ __launch_bounds__(128) void agg_h8_csr(
    int N, const int* __restrict__ rowptr, const int* __restrict__ srcs,
    const float* __restrict__ h, const float* __restrict__ als,
    const float* __restrict__ ald, const float* __restrict__ bias,
    float* __restrict__ out) {
    int d = blockIdx.x;
    int t = threadIdx.x;
    int hh = t >> 4;
    float aldv = __ldg(&ald[d * 8 + hh]);

    float ex = __expf(leaky(__ldg(&als[d * 8 + hh]) + aldv));
    float den = ex;
    float4 acc = ((const float4*)(h + (size_t)d * 512))[t];
    acc.x *= ex; acc.y *= ex; acc.z *= ex; acc.w *= ex;

    int beg = rowptr[d], end = rowptr[d + 1];
    int p = beg;
    for (; p + 2 <= end; p += 2) {
        int s0 = srcs[p], s1 = srcs[p + 1];
        float e0 = __expf(leaky(__ldg(&als[s0 * 8 + hh]) + aldv));
        float e1 = __expf(leaky(__ldg(&als[s1 * 8 + hh]) + aldv));
        float4 v0 = ((const float4*)(h + (size_t)s0 * 512))[t];
        float4 v1 = ((const float4*)(h + (size_t)s1 * 512))[t];
        den += e0 + e1;
        acc.x += e0 * v0.x + e1 * v1.x;
        acc.y += e0 * v0.y + e1 * v1.y;
        acc.z += e0 * v0.z + e1 * v1.z;
        acc.w += e0 * v0.w + e1 * v1.w;
    }
    if (p < end) {
        int s0 = srcs[p];
        float e0 = __expf(leaky(__ldg(&als[s0 * 8 + hh]) + aldv));
        float4 v0 = ((const float4*)(h + (size_t)s0 * 512))[t];
        den += e0;
        acc.x += e0 * v0.x; acc.y += e0 * v0.y;
        acc.z += e0 * v0.z; acc.w += e0 * v0.w;
    }
    float inv = 1.0f / den;
    float4 b = ((const float4*)bias)[t];
    float4 r;
    r.x = elu(acc.x * inv + b.x);
    r.y = elu(acc.y * inv + b.y);
    r.z = elu(acc.z * inv + b.z);
    r.w = elu(acc.w * inv + b.w);
    ((float4*)(out + (size_t)d * 512))[t] = r;
}

// Fused softmax+aggregate+bias+ELU, H=1,C=64. One warp per node.
__global__ __launch_bounds__(256) void agg_h1_csr(
    int N, const int* __restrict__ rowptr, const int* __restrict__ srcs,
    const float* __restrict__ h, const float* __restrict__ als,
    const float* __restrict__ ald, const float* __restrict__ bias,
    float* __restrict__ out) {
    int w = (blockIdx.x * blockDim.x + threadIdx.x) >> 5;
    int lane = threadIdx.x & 31;
    if (w >= N) return;
    int d = w;
    float aldv = __ldg(&ald[d]);

    float ex = __expf(leaky(__ldg(&als[d]) + aldv));
    float den = ex;
    float2 acc = ((const float2*)(h + (size_t)d * 64))[lane];
    acc.x *= ex; acc.y *= ex;

    int beg = rowptr[d], end = rowptr[d + 1];
    int p = beg;
    for (; p + 2 <= end; p += 2) {
        int s0 = srcs[p], s1 = srcs[p + 1];
        float e0 = __expf(leaky(__ldg(&als[s0]) + aldv));
        float e1 = __expf(leaky(__ldg(&als[s1]) + aldv));
        float2 v0 = ((const float2*)(h + (size_t)s0 * 64))[lane];
        float2 v1 = ((const float2*)(h + (size_t)s1 * 64))[lane];
        den += e0 + e1;
        acc.x += e0 * v0.x + e1 * v1.x;
        acc.y += e0 * v0.y + e1 * v1.y;
    }
    if (p < end) {
        int s0 = srcs[p];
        float e0 = __expf(leaky(__ldg(&als[s0]) + aldv));
        float2 v0 = ((const float2*)(h + (size_t)s0 * 64))[lane];
        den += e0;
        acc.x += e0 * v0.x; acc.y += e0 * v0.y;
    }
    float inv = 1.0f / den;
    float2 b = ((const float2*)bias)[lane];
    float2 r;
    r.x = elu(acc.x * inv + b.x);
    r.y = elu(acc.y * inv + b.y);
    ((float2*)(out + (size_t)d * 64))[lane] = r;
}

// ---------------------------------------------------------------------------
// Pool (run-length over sorted batch) + FC
// ---------------------------------------------------------------------------
__global__ void pool2_k(const float* __restrict__ h, const int* __restrict__ batch,
                        float* gsum, float* gcnt, int N) {
    int c = threadIdx.x & 63;
    int sub = threadIdx.x >> 6;
    int base = blockIdx.x * 64 + sub * 16;
    float acc = 0.f, cnt = 0.f;
    int curg = -1;
    for (int i = 0; i < 16; i++) {
        int n = base + i;
        if (n >= N) break;
        int gg = batch[n];
        if (gg != curg) {
            if (curg >= 0) {
                atomicAdd(&gsum[curg * 64 + c], acc);
                if (c == 0) atomicAdd(&gcnt[curg], cnt);
            }
            curg = gg; acc = 0.f; cnt = 0.f;
        }
        acc += h[(size_t)n * 64 + c];
        cnt += 1.f;
    }
    if (curg >= 0) {
        atomicAdd(&gsum[curg * 64 + c], acc);
        if (c == 0) atomicAdd(&gcnt[curg], cnt);
    }
}

__global__ void fc_k(const float* __restrict__ gsum, const float* __restrict__ gcnt,
                     const float* __restrict__ W, const float* __restrict__ b,
                     float* __restrict__ out) {
    int t = blockIdx.x * blockDim.x + threadIdx.x;
    if (t >= 640) return;
    int g = t / 10, o = t % 10;
    float inv = 1.0f / fmaxf(gcnt[g], 1.0f);
    float s = 0.f;
#pragma unroll
    for (int c = 0; c < 64; c++) s += (gsum[g * 64 + c] * inv) * W[c * 10 + o];
    out[t] = s + b[o];
}

// ---------------------------------------------------------------------------
// Host side
// ---------------------------------------------------------------------------
static inline void* symptr(const void* sym) {
    void* p = nullptr;
    cudaGetSymbolAddress(&p, sym);
    return p;
}
static inline int cdiv(long a, int b) { return (int)((a + b - 1) / b); }

extern "C" void kernel_launch(void* const* d_in, const int* in_sizes, int n_in,
                              void* d_out, int out_size) {
    const float* x   = (const float*)d_in[0];
    const int*   ei  = (const int*)d_in[1];
    const int*   bat = (const int*)d_in[2];
    const float* W1  = (const float*)d_in[3];
    const float* a1s = (const float*)d_in[4];
    const float* a1d = (const float*)d_in[5];
    const float* b1  = (const float*)d_in[6];
    const float* W2  = (const float*)d_in[7];
    const float* a2s = (const float*)d_in[8];
    const float* a2d = (const float*)d_in[9];
    const float* b2  = (const float*)d_in[10];
    const float* W3  = (const float*)d_in[11];
    const float* a3s = (const float*)d_in[12];
    const float* a3d = (const float*)d_in[13];
    const float* b3  = (const float*)d_in[14];
    const float* fcW = (const float*)d_in[15];
    const float* fcb = (const float*)d_in[16];

    const int N = in_sizes[0] / 128;
    const int E = in_sizes[1] / 2;

    float* bufA   = (float*)symptr(g_bufA);
    float* bufB   = (float*)symptr(g_bufB);
    float* als    = (float*)symptr(g_als);
    float* ald    = (float*)symptr(g_ald);
    int*   deg    = (int*)symptr(g_deg);
    int*   incl   = (int*)symptr(g_incl);
    int*   bsum   = (int*)symptr(g_bsum);
    int*   bsumex = (int*)symptr(g_bsumex);
    int*   rowptr = (int*)symptr(g_rowptr);
    int*   cnt    = (int*)symptr(g_cnt);
    int*   srcs   = (int*)symptr(g_srcs);
    float* gsum   = (float*)symptr(g_gsum);
    float* gcnt   = (float*)symptr(g_gcnt);

    const int TB = 256;
    const int nScanB = cdiv(N, SCAN_B);

    // ---------------- CSR build ----------------
    filli_k<<<cdiv(N, TB), TB>>>(deg, N, 0);
    filli_k<<<cdiv(N, TB), TB>>>(cnt, N, 0);
    hist_k<<<cdiv(E, TB), TB>>>(E, ei, deg);
    scan1_k<<<nScanB, SCAN_B>>>(deg, incl, bsum, N);
    scan2_k<<<1, 32>>>(bsum, bsumex, nScanB, rowptr);
    scan3_k<<<cdiv(N, TB), TB>>>(incl, bsumex, rowptr, N);
    scatter_k<<<cdiv(E, TB), TB>>>(E, ei, rowptr, cnt, srcs);

    // ---------------- Layer 1 (H=8, C=64, in=128) ----------------
    {
        dim3 grid(512 / 64, cdiv(N, 128));
        tf32gemm_k<<<grid, 256>>>(N, 512, 128, x, W1, bufA);
    }
    compute_al_k<8, 64><<<cdiv((long)N * 8 * 32, TB), TB>>>(N, bufA, a1s, a1d, als, ald);
    agg_h8_csr<<<N, 128>>>(N, rowptr, srcs, bufA, als, ald, b1, bufB);

    // ---------------- Layer 2 (H=1, C=64, in=512) ----------------
    {
        dim3 grid(1, cdiv(N, 128));
        tf32gemm_k<<<grid, 256>>>(N, 64, 512, bufB, W2, bufA);
    }
    compute_al_k<1, 64><<<cdiv((long)N * 32, TB), TB>>>(N, bufA, a2s, a2d, als, ald);
    agg_h1_csr<<<cdiv(N, 8), 256>>>(N, rowptr, srcs, bufA, als, ald, b2, bufB);

    // ---------------- Layer 3 (H=1, C=64, in=64) ----------------
    {
        dim3 grid(1, cdiv(N, 128));
        tf32gemm_k<<<grid, 256>>>(N, 64, 64, bufB, W3, bufA);
    }
    compute_al_k<1, 64><<<cdiv((long)N * 32, TB), TB>>>(N, bufA, a3s, a3d, als, ald);
    agg_h1_csr<<<cdiv(N, 8), 256>>>(N, rowptr, srcs, bufA, als, ald, b3, bufB);

    // ---------------- Pool + FC ----------------
    fillf_k<<<16, 256>>>(gsum, 64 * 64, 0.f);
    fillf_k<<<1, 64>>>(gcnt, 64, 0.f);
    pool2_k<<<cdiv(N, 64), 256>>>(bufB, bat, gsum, gcnt, N);
    fc_k<<<3, 256>>>(gsum, gcnt, fcW, fcb, (float*)d_out);
}